// round 3
// baseline (speedup 1.0000x reference)
#include <cuda_runtime.h>
#include <math.h>
#include <stdint.h>

#define Bz 2
#define Tz 1024
#define Cz 1024
#define Hz 16
#define HDz 64
#define Lz 12
#define Vz 50257
#define BTz (Bz*Tz)
#define C4z (4*Cz)

// ---------------- scratch (device globals; no allocation) ----------------
__device__ float g_x[BTz*Cz];       // residual stream
__device__ float g_h[BTz*Cz];       // LN output
__device__ float g_q[BTz*Cz];
__device__ float g_k[BTz*Cz];
__device__ float g_v[BTz*Cz];
__device__ float g_y[BTz*Cz];       // attention output (pre-proj)
__device__ float g_ff[(size_t)BTz*C4z];     // MLP hidden
__device__ float g_att[(size_t)Bz*Hz*Tz*Tz]; // attention probs
__device__ float g_red[BTz];        // per-row NLL

// ---------------- block reductions ----------------
__device__ __forceinline__ float blockReduceSum(float v) {
    __shared__ float sh[33];
    int lane = threadIdx.x & 31, w = threadIdx.x >> 5;
    #pragma unroll
    for (int o = 16; o; o >>= 1) v += __shfl_down_sync(0xffffffffu, v, o);
    __syncthreads();
    if (lane == 0) sh[w] = v;
    __syncthreads();
    if (threadIdx.x == 0) {
        float s = 0.f;
        int nw = blockDim.x >> 5;
        for (int i = 0; i < nw; i++) s += sh[i];
        sh[32] = s;
    }
    __syncthreads();
    return sh[32];
}

__device__ __forceinline__ float blockReduceMax(float v) {
    __shared__ float sh[33];
    int lane = threadIdx.x & 31, w = threadIdx.x >> 5;
    #pragma unroll
    for (int o = 16; o; o >>= 1) v = fmaxf(v, __shfl_down_sync(0xffffffffu, v, o));
    __syncthreads();
    if (lane == 0) sh[w] = v;
    __syncthreads();
    if (threadIdx.x == 0) {
        float s = -1e30f;
        int nw = blockDim.x >> 5;
        for (int i = 0; i < nw; i++) s = fmaxf(s, sh[i]);
        sh[32] = s;
    }
    __syncthreads();
    return sh[32];
}

// ---------------- embedding ----------------
__global__ void embed_kernel(const int* __restrict__ idx,
                             const float* __restrict__ tok,
                             const float* __restrict__ pos) {
    int r = blockIdx.x;
    int c = threadIdx.x * 4;
    int tokid = idx[r];
    float4 te = *(const float4*)(tok + (size_t)tokid * Cz + c);
    float4 pe = *(const float4*)(pos + (size_t)(r % Tz) * Cz + c);
    float4 o;
    o.x = te.x + pe.x; o.y = te.y + pe.y; o.z = te.z + pe.z; o.w = te.w + pe.w;
    *(float4*)(g_x + (size_t)r * Cz + c) = o;
}

// ---------------- layernorm (one block per row, C=1024, 256 thr) ----------------
__global__ void ln_kernel(const float* __restrict__ x,
                          const float* __restrict__ w,
                          const float* __restrict__ b,
                          float* __restrict__ out) {
    int r = blockIdx.x;
    const float* xr = x + (size_t)r * Cz;
    float v[4];
    #pragma unroll
    for (int k = 0; k < 4; k++) v[k] = xr[threadIdx.x + k * 256];
    float s = v[0] + v[1] + v[2] + v[3];
    s = blockReduceSum(s);
    float mu = s * (1.0f / Cz);
    float sq = 0.f;
    #pragma unroll
    for (int k = 0; k < 4; k++) { float d = v[k] - mu; sq += d * d; }
    sq = blockReduceSum(sq);
    float rstd = rsqrtf(sq * (1.0f / Cz) + 1e-5f);
    float* orow = out + (size_t)r * Cz;
    #pragma unroll
    for (int k = 0; k < 4; k++) {
        int c = threadIdx.x + k * 256;
        orow[c] = (v[k] - mu) * rstd * w[c] + b[c];
    }
}

// ---------------- generic SGEMM: C = A[MxK] @ B[KxN] (+bias)(+gelu)(+res) ----------------
// VECB: B rows are 16B-aligned and N%4==0 -> float4 loads; otherwise scalar loads
#define GBM 128
#define GBN 128
#define GBK 16
template<bool GELU, bool VECB>
__global__ void gemm_kernel(const float* __restrict__ A, const float* __restrict__ Bm,
                            const float* __restrict__ bias, const float* __restrict__ res,
                            float* __restrict__ Cout, int M, int N, int K) {
    __shared__ float As[GBK][GBM];
    __shared__ float Bs[GBK][GBN + 4];
    int tid = threadIdx.x;
    int rowBlk = blockIdx.y * GBM;
    int colBlk = blockIdx.x * GBN;
    int tx = tid & 15, ty = tid >> 4;
    float acc[8][8] = {};
    int aRow  = tid >> 2;            // 0..63
    int aCol4 = (tid & 3) * 4;       // 0,4,8,12
    int bRow  = tid >> 5;            // 0..7
    int bCol  = (tid & 31) * 4;      // 0..124
    for (int k0 = 0; k0 < K; k0 += GBK) {
        #pragma unroll
        for (int r = 0; r < 2; r++) {
            int m = aRow + r * 64;
            float4 av = *(const float4*)(A + (size_t)(rowBlk + m) * K + k0 + aCol4);
            As[aCol4 + 0][m] = av.x;
            As[aCol4 + 1][m] = av.y;
            As[aCol4 + 2][m] = av.z;
            As[aCol4 + 3][m] = av.w;
        }
        #pragma unroll
        for (int r = 0; r < 2; r++) {
            int kk = bRow + r * 8;
            int nb = colBlk + bCol;
            const float* bp = Bm + (size_t)(k0 + kk) * N + nb;
            float4 bv;
            if (VECB) {
                bv = *(const float4*)bp;
            } else {
                // scalar loads: always 4B-aligned, safe for odd N (e.g. V=50257)
                bv.x = (nb + 0 < N) ? bp[0] : 0.f;
                bv.y = (nb + 1 < N) ? bp[1] : 0.f;
                bv.z = (nb + 2 < N) ? bp[2] : 0.f;
                bv.w = (nb + 3 < N) ? bp[3] : 0.f;
            }
            *(float4*)&Bs[kk][bCol] = bv;
        }
        __syncthreads();
        #pragma unroll
        for (int k = 0; k < GBK; k++) {
            float rm[8], rn[8];
            #pragma unroll
            for (int i = 0; i < 8; i++) rm[i] = As[k][ty * 8 + i];
            #pragma unroll
            for (int j = 0; j < 8; j++) rn[j] = Bs[k][tx * 8 + j];
            #pragma unroll
            for (int i = 0; i < 8; i++)
                #pragma unroll
                for (int j = 0; j < 8; j++)
                    acc[i][j] += rm[i] * rn[j];
        }
        __syncthreads();
    }
    #pragma unroll
    for (int i = 0; i < 8; i++) {
        int row = rowBlk + ty * 8 + i;
        #pragma unroll
        for (int j = 0; j < 8; j++) {
            int col = colBlk + tx * 8 + j;
            if (col < N) {
                float v = acc[i][j];
                if (bias) v += bias[col];
                if (GELU) v = 0.5f * v * (1.0f + erff(v * 0.7071067811865476f));
                if (res)  v += res[(size_t)row * N + col];
                Cout[(size_t)row * N + col] = v;
            }
        }
    }
}

// ---------------- attention: S = scale * Q Kt, causal blocks only ----------------
__global__ void attn_scores_kernel() {
    int bx = blockIdx.x;   // key block
    int by = blockIdx.y;   // query block
    if (bx > by) return;   // fully masked
    int bh = blockIdx.z;
    int b = bh / Hz, h = bh % Hz;
    __shared__ float sQ[64][65];
    __shared__ float sK[64][65];
    int tid = threadIdx.x;
    int lr = tid >> 4;
    int lc = (tid & 15) * 4;
    #pragma unroll
    for (int r = 0; r < 4; r++) {
        int row = lr + r * 16;
        float4 qv = *(const float4*)(g_q + (size_t)(b * Tz + by * 64 + row) * Cz + h * HDz + lc);
        sQ[row][lc] = qv.x; sQ[row][lc + 1] = qv.y; sQ[row][lc + 2] = qv.z; sQ[row][lc + 3] = qv.w;
        float4 kv = *(const float4*)(g_k + (size_t)(b * Tz + bx * 64 + row) * Cz + h * HDz + lc);
        sK[row][lc] = kv.x; sK[row][lc + 1] = kv.y; sK[row][lc + 2] = kv.z; sK[row][lc + 3] = kv.w;
    }
    __syncthreads();
    int tx = tid & 15, ty = tid >> 4;
    float acc[4][4] = {};
    #pragma unroll
    for (int d = 0; d < 64; d++) {
        float rm[4], rn[4];
        #pragma unroll
        for (int i = 0; i < 4; i++) rm[i] = sQ[ty * 4 + i][d];
        #pragma unroll
        for (int j = 0; j < 4; j++) rn[j] = sK[tx * 4 + j][d];
        #pragma unroll
        for (int i = 0; i < 4; i++)
            #pragma unroll
            for (int j = 0; j < 4; j++)
                acc[i][j] += rm[i] * rn[j];
    }
    const float scale = 0.125f; // 1/sqrt(64)
    #pragma unroll
    for (int i = 0; i < 4; i++) {
        size_t base = ((size_t)bh * Tz + by * 64 + ty * 4 + i) * Tz + bx * 64 + tx * 4;
        #pragma unroll
        for (int j = 0; j < 4; j++)
            g_att[base + j] = acc[i][j] * scale;
    }
}

// ---------------- causal softmax, one block per (b,h,query-row) ----------------
__global__ void softmax_kernel() {
    int m = blockIdx.x;            // (b*H + h)*T + i
    int i = m % Tz;
    float* row = g_att + (size_t)m * Tz;
    int n = i + 1;
    int tid = threadIdx.x;
    float mx = -1e30f;
    for (int j = tid; j < n; j += 256) mx = fmaxf(mx, row[j]);
    mx = blockReduceMax(mx);
    float s = 0.f;
    for (int j = tid; j < n; j += 256) {
        float e = expf(row[j] - mx);
        row[j] = e;
        s += e;
    }
    s = blockReduceSum(s);
    float inv = 1.0f / s;
    for (int j = tid; j < n; j += 256) row[j] *= inv;
    for (int j = n + tid; j < Tz; j += 256) row[j] = 0.f;   // zero masked region
}

// ---------------- Y = att @ V (K-loop stops at diagonal block) ----------------
__global__ void attn_av_kernel() {
    int by = blockIdx.x;   // query block
    int bh = blockIdx.y;
    int b = bh / Hz, h = bh % Hz;
    __shared__ float sA[64][65];
    __shared__ float sV[64][65];
    int tid = threadIdx.x;
    int lr = tid >> 4;
    int lc = (tid & 15) * 4;
    int tx = tid & 15, ty = tid >> 4;
    float acc[4][4] = {};
    for (int kt = 0; kt <= by; kt++) {
        #pragma unroll
        for (int r = 0; r < 4; r++) {
            int row = lr + r * 16;
            float4 av = *(const float4*)(g_att + ((size_t)bh * Tz + by * 64 + row) * Tz + kt * 64 + lc);
            sA[row][lc] = av.x; sA[row][lc + 1] = av.y; sA[row][lc + 2] = av.z; sA[row][lc + 3] = av.w;
            float4 vv = *(const float4*)(g_v + (size_t)(b * Tz + kt * 64 + row) * Cz + h * HDz + lc);
            sV[row][lc] = vv.x; sV[row][lc + 1] = vv.y; sV[row][lc + 2] = vv.z; sV[row][lc + 3] = vv.w;
        }
        __syncthreads();
        #pragma unroll
        for (int j = 0; j < 64; j++) {
            float rm[4], rn[4];
            #pragma unroll
            for (int i = 0; i < 4; i++) rm[i] = sA[ty * 4 + i][j];
            #pragma unroll
            for (int d = 0; d < 4; d++) rn[d] = sV[j][tx * 4 + d];
            #pragma unroll
            for (int i = 0; i < 4; i++)
                #pragma unroll
                for (int d = 0; d < 4; d++)
                    acc[i][d] += rm[i] * rn[d];
        }
        __syncthreads();
    }
    #pragma unroll
    for (int i = 0; i < 4; i++)
        #pragma unroll
        for (int d = 0; d < 4; d++)
            g_y[(size_t)(b * Tz + by * 64 + ty * 4 + i) * Cz + h * HDz + tx * 4 + d] = acc[i][d];
}

// ---------------- loss: per-row log-sum-exp NLL over V ----------------
__global__ void loss_row_kernel(const float* __restrict__ logits,
                                const int* __restrict__ targets) {
    int r = blockIdx.x;
    const float* row = logits + (size_t)r * Vz;
    int tid = threadIdx.x;
    float mx = -1e30f;
    for (int j = tid; j < Vz; j += 256) mx = fmaxf(mx, row[j]);
    mx = blockReduceMax(mx);
    float s = 0.f;
    for (int j = tid; j < Vz; j += 256) s += expf(row[j] - mx);
    s = blockReduceSum(s);
    if (tid == 0) {
        int t = targets[r];
        g_red[r] = -(row[t] - mx - logf(s));
    }
}

__global__ void loss_final_kernel(float* __restrict__ out, int out_size) {
    int tid = threadIdx.x;
    float s = 0.f;
    for (int j = tid; j < BTz; j += 256) s += g_red[j];
    s = blockReduceSum(s);
    if (tid == 0) {
        long long logits_elems = (long long)BTz * Vz;
        if ((long long)out_size > logits_elems)
            out[logits_elems] = s / (float)BTz;
    }
}

// ---------------- launch ----------------
extern "C" void kernel_launch(void* const* d_in, const int* in_sizes, int n_in,
                              void* d_out, int out_size) {
    const int*   idx     = (const int*)d_in[0];
    const int*   targets = (const int*)d_in[1];
    const float* tok_emb = (const float*)d_in[2];
    const float* pos_emb = (const float*)d_in[3];
    const float* ln1_w   = (const float*)d_in[4];
    const float* ln1_b   = (const float*)d_in[5];
    const float* ln2_w   = (const float*)d_in[6];
    const float* ln2_b   = (const float*)d_in[7];
    const float* Wq = (const float*)d_in[8];
    const float* bq = (const float*)d_in[9];
    const float* Wk = (const float*)d_in[10];
    const float* bk = (const float*)d_in[11];
    const float* Wv = (const float*)d_in[12];
    const float* bv = (const float*)d_in[13];
    const float* Wo = (const float*)d_in[14];
    const float* bo = (const float*)d_in[15];
    const float* W1 = (const float*)d_in[16];
    const float* b1 = (const float*)d_in[17];
    const float* W2 = (const float*)d_in[18];
    const float* b2 = (const float*)d_in[19];
    const float* lnf_w  = (const float*)d_in[20];
    const float* lnf_b  = (const float*)d_in[21];
    const float* head_w = (const float*)d_in[22];
    float* out = (float*)d_out;

    float *px, *ph, *pq, *pk, *pv, *py, *pff;
    cudaGetSymbolAddress((void**)&px,  g_x);
    cudaGetSymbolAddress((void**)&ph,  g_h);
    cudaGetSymbolAddress((void**)&pq,  g_q);
    cudaGetSymbolAddress((void**)&pk,  g_k);
    cudaGetSymbolAddress((void**)&pv,  g_v);
    cudaGetSymbolAddress((void**)&py,  g_y);
    cudaGetSymbolAddress((void**)&pff, g_ff);

    embed_kernel<<<BTz, 256>>>(idx, tok_emb, pos_emb);

    const size_t CC  = (size_t)Cz * Cz;
    const size_t C14 = (size_t)Cz * C4z;

    for (int l = 0; l < Lz; l++) {
        ln_kernel<<<BTz, 256>>>(px, ln1_w + (size_t)l * Cz, ln1_b + (size_t)l * Cz, ph);
        gemm_kernel<false, true><<<dim3(8, 16), 256>>>(ph, Wq + l * CC, bq + (size_t)l * Cz, nullptr, pq, BTz, Cz, Cz);
        gemm_kernel<false, true><<<dim3(8, 16), 256>>>(ph, Wk + l * CC, bk + (size_t)l * Cz, nullptr, pk, BTz, Cz, Cz);
        gemm_kernel<false, true><<<dim3(8, 16), 256>>>(ph, Wv + l * CC, bv + (size_t)l * Cz, nullptr, pv, BTz, Cz, Cz);
        attn_scores_kernel<<<dim3(16, 16, Bz * Hz), 256>>>();
        softmax_kernel<<<Bz * Hz * Tz, 256>>>();
        attn_av_kernel<<<dim3(16, Bz * Hz), 256>>>();
        gemm_kernel<false, true><<<dim3(8, 16), 256>>>(py, Wo + l * CC, bo + (size_t)l * Cz, px, px, BTz, Cz, Cz);
        ln_kernel<<<BTz, 256>>>(px, ln2_w + (size_t)l * Cz, ln2_b + (size_t)l * Cz, ph);
        gemm_kernel<true , true><<<dim3(32, 16), 256>>>(ph, W1 + l * C14, b1 + (size_t)l * C4z, nullptr, pff, BTz, C4z, Cz);
        gemm_kernel<false, true><<<dim3(8, 16), 256>>>(pff, W2 + l * C14, b2 + (size_t)l * Cz, px, px, BTz, Cz, C4z);
    }

    ln_kernel<<<BTz, 256>>>(px, lnf_w, lnf_b, ph);
    // head GEMM: N = V = 50257 (odd) -> B rows not 16B-aligned -> scalar B loads
    gemm_kernel<false, false><<<dim3((Vz + GBN - 1) / GBN, 16), 256>>>(ph, head_w, nullptr, nullptr, out, BTz, Vz, Cz);
    loss_row_kernel<<<BTz, 256>>>(out, targets);
    loss_final_kernel<<<1, 256>>>(out, out_size);
}

// round 4
// speedup vs baseline: 1.4870x; 1.4870x over previous
#include <cuda_runtime.h>
#include <cuda_bf16.h>
#include <math.h>
#include <stdint.h>

#define Bz 2
#define Tz 1024
#define Cz 1024
#define Hz 16
#define HDz 64
#define Lz 12
#define Vz 50257
#define BTz (Bz*Tz)
#define C4z (4*Cz)

// ---------------- scratch (device globals; no allocation) ----------------
__device__ float g_x[BTz*Cz];
__device__ float g_h[BTz*Cz];
__device__ float g_q[BTz*Cz];
__device__ float g_k[BTz*Cz];
__device__ float g_v[BTz*Cz];
__device__ float g_y[BTz*Cz];
__device__ float g_ff[(size_t)BTz*C4z];
__device__ float g_att[(size_t)Bz*Hz*Tz*Tz];
__device__ float g_red[BTz];

// ---------------- block reductions ----------------
__device__ __forceinline__ float blockReduceSum(float v) {
    __shared__ float sh[33];
    int lane = threadIdx.x & 31, w = threadIdx.x >> 5;
    #pragma unroll
    for (int o = 16; o; o >>= 1) v += __shfl_down_sync(0xffffffffu, v, o);
    __syncthreads();
    if (lane == 0) sh[w] = v;
    __syncthreads();
    if (threadIdx.x == 0) {
        float s = 0.f;
        int nw = blockDim.x >> 5;
        for (int i = 0; i < nw; i++) s += sh[i];
        sh[32] = s;
    }
    __syncthreads();
    return sh[32];
}

__device__ __forceinline__ float blockReduceMax(float v) {
    __shared__ float sh[33];
    int lane = threadIdx.x & 31, w = threadIdx.x >> 5;
    #pragma unroll
    for (int o = 16; o; o >>= 1) v = fmaxf(v, __shfl_down_sync(0xffffffffu, v, o));
    __syncthreads();
    if (lane == 0) sh[w] = v;
    __syncthreads();
    if (threadIdx.x == 0) {
        float s = -1e30f;
        int nw = blockDim.x >> 5;
        for (int i = 0; i < nw; i++) s = fmaxf(s, sh[i]);
        sh[32] = s;
    }
    __syncthreads();
    return sh[32];
}

// ---------------- embedding ----------------
__global__ void embed_kernel(const int* __restrict__ idx,
                             const float* __restrict__ tok,
                             const float* __restrict__ pos) {
    int r = blockIdx.x;
    int c = threadIdx.x * 4;
    int tokid = idx[r];
    float4 te = *(const float4*)(tok + (size_t)tokid * Cz + c);
    float4 pe = *(const float4*)(pos + (size_t)(r % Tz) * Cz + c);
    float4 o;
    o.x = te.x + pe.x; o.y = te.y + pe.y; o.z = te.z + pe.z; o.w = te.w + pe.w;
    *(float4*)(g_x + (size_t)r * Cz + c) = o;
}

// ---------------- layernorm ----------------
__global__ void ln_kernel(const float* __restrict__ x,
                          const float* __restrict__ w,
                          const float* __restrict__ b,
                          float* __restrict__ out) {
    int r = blockIdx.x;
    const float* xr = x + (size_t)r * Cz;
    float v[4];
    #pragma unroll
    for (int k = 0; k < 4; k++) v[k] = xr[threadIdx.x + k * 256];
    float s = v[0] + v[1] + v[2] + v[3];
    s = blockReduceSum(s);
    float mu = s * (1.0f / Cz);
    float sq = 0.f;
    #pragma unroll
    for (int k = 0; k < 4; k++) { float d = v[k] - mu; sq += d * d; }
    sq = blockReduceSum(sq);
    float rstd = rsqrtf(sq * (1.0f / Cz) + 1e-5f);
    float* orow = out + (size_t)r * Cz;
    #pragma unroll
    for (int k = 0; k < 4; k++) {
        int c = threadIdx.x + k * 256;
        orow[c] = (v[k] - mu) * rstd * w[c] + b[c];
    }
}

// =========================================================================
// Tensor-core GEMM: C = A[MxK] @ B[KxN] (+bias)(+gelu)(+res), fp32 in/out.
// hi/lo bf16 split: a = ah + al (al = bf16(a - ah)).
// K expanded 3x in SMEM:  A'' = [ (ah,al) interleaved | ah ],
//                         B'' = [ (bh,bh) interleaved | bl ]
// -> sum over K'' = sum(ah*bh + al*bh + ah*bl): error ~2^-17 per product.
// Block tile 128x128, K-tile 32 fp32 (K''=96). 8 warps, warp tile 64x32.
// =========================================================================
#define MBM 128
#define MBN 128
#define MBK 32          // fp32 k per iteration
#define MBK3 96         // expanded bf16 k
#define MLDS 98         // row stride (bf16) -> 49 words, odd: conflict-free frags

__device__ __forceinline__ void mma16816(float4& c, uint32_t a0, uint32_t a1,
                                         uint32_t a2, uint32_t a3,
                                         uint32_t b0, uint32_t b1) {
    asm volatile(
        "mma.sync.aligned.m16n8k16.row.col.f32.bf16.bf16.f32 "
        "{%0,%1,%2,%3}, {%4,%5,%6,%7}, {%8,%9}, {%0,%1,%2,%3};"
        : "+f"(c.x), "+f"(c.y), "+f"(c.z), "+f"(c.w)
        : "r"(a0), "r"(a1), "r"(a2), "r"(a3), "r"(b0), "r"(b1));
}

template<bool GELU, bool VECB>
__global__ void __launch_bounds__(256, 2)
gemm_mma_kernel(const float* __restrict__ A, const float* __restrict__ Bm,
                const float* __restrict__ bias, const float* __restrict__ res,
                float* __restrict__ Cout, int M, int N, int K) {
    extern __shared__ __nv_bfloat16 smem[];
    __nv_bfloat16* As = smem;                 // [128][MLDS]
    __nv_bfloat16* Bs = smem + MBM * MLDS;    // [128][MLDS] (n-major)

    int tid = threadIdx.x;
    int lane = tid & 31;
    int warp = tid >> 5;
    int wm = warp & 1;        // 2 warps along M (64 rows each)
    int wn = warp >> 1;       // 4 warps along N (32 cols each)
    int g  = lane >> 2;       // 0..7
    int tg = lane & 3;        // 0..3

    int rowBlk = blockIdx.y * MBM;
    int colBlk = blockIdx.x * MBN;

    // staging mapping
    int stRowA = tid >> 1;            // 0..127
    int stSegA = (tid & 1) * 16;      // 0 or 16 (fp32 cols)
    int stKfB  = tid >> 5;            // 0..7 (row within pass)
    int stNB   = (tid & 31) * 4;      // 0..124

    float4 acc[4][4];
    #pragma unroll
    for (int i = 0; i < 4; i++)
        #pragma unroll
        for (int j = 0; j < 4; j++) acc[i][j] = make_float4(0.f, 0.f, 0.f, 0.f);

    for (int k0 = 0; k0 < K; k0 += MBK) {
        // ---- stage A tile (128 x 32 fp32 -> split bf16) ----
        {
            const float* ap = A + (size_t)(rowBlk + stRowA) * K + k0 + stSegA;
            #pragma unroll
            for (int i = 0; i < 4; i++) {
                float4 v = *(const float4*)(ap + i * 4);
                float xs[4] = {v.x, v.y, v.z, v.w};
                #pragma unroll
                for (int e = 0; e < 4; e++) {
                    int kf = stSegA + i * 4 + e;
                    float x = xs[e];
                    __nv_bfloat16 hi = __float2bfloat16(x);
                    __nv_bfloat16 lo = __float2bfloat16(x - __bfloat162float(hi));
                    __nv_bfloat162 p; p.x = hi; p.y = lo;
                    *reinterpret_cast<__nv_bfloat162*>(&As[stRowA * MLDS + 2 * kf]) = p;
                    As[stRowA * MLDS + 64 + kf] = hi;
                }
            }
        }
        // ---- stage B tile (32 x 128 fp32 -> split bf16, n-major) ----
        #pragma unroll
        for (int p = 0; p < 4; p++) {
            int kf = p * 8 + stKfB;
            int nb = colBlk + stNB;
            const float* bp = Bm + (size_t)(k0 + kf) * N + nb;
            float xs[4];
            if (VECB) {
                float4 v = *(const float4*)bp;
                xs[0] = v.x; xs[1] = v.y; xs[2] = v.z; xs[3] = v.w;
            } else {
                #pragma unroll
                for (int e = 0; e < 4; e++) xs[e] = (nb + e < N) ? bp[e] : 0.f;
            }
            #pragma unroll
            for (int e = 0; e < 4; e++) {
                float x = xs[e];
                __nv_bfloat16 hi = __float2bfloat16(x);
                __nv_bfloat16 lo = __float2bfloat16(x - __bfloat162float(hi));
                __nv_bfloat162 pq; pq.x = hi; pq.y = hi;
                *reinterpret_cast<__nv_bfloat162*>(&Bs[(stNB + e) * MLDS + 2 * kf]) = pq;
                Bs[(stNB + e) * MLDS + 64 + kf] = lo;
            }
        }
        __syncthreads();

        // ---- mma over K'' = 96 (6 steps of 16) ----
        #pragma unroll
        for (int ks = 0; ks < 6; ks++) {
            int kb = ks * 16;
            uint32_t ra[4][4];
            #pragma unroll
            for (int mf = 0; mf < 4; mf++) {
                int r0 = wm * 64 + mf * 16 + g;
                const __nv_bfloat16* base = &As[(size_t)r0 * MLDS + kb + tg * 2];
                ra[mf][0] = *reinterpret_cast<const uint32_t*>(base);
                ra[mf][1] = *reinterpret_cast<const uint32_t*>(base + 8 * MLDS);
                ra[mf][2] = *reinterpret_cast<const uint32_t*>(base + 8);
                ra[mf][3] = *reinterpret_cast<const uint32_t*>(base + 8 * MLDS + 8);
            }
            uint32_t rb[4][2];
            #pragma unroll
            for (int nf = 0; nf < 4; nf++) {
                int nc = wn * 32 + nf * 8 + g;
                const __nv_bfloat16* base = &Bs[(size_t)nc * MLDS + kb + tg * 2];
                rb[nf][0] = *reinterpret_cast<const uint32_t*>(base);
                rb[nf][1] = *reinterpret_cast<const uint32_t*>(base + 8);
            }
            #pragma unroll
            for (int mf = 0; mf < 4; mf++)
                #pragma unroll
                for (int nf = 0; nf < 4; nf++)
                    mma16816(acc[mf][nf], ra[mf][0], ra[mf][1], ra[mf][2], ra[mf][3],
                             rb[nf][0], rb[nf][1]);
        }
        __syncthreads();
    }

    // ---- epilogue ----
    #pragma unroll
    for (int mf = 0; mf < 4; mf++) {
        int row0 = rowBlk + wm * 64 + mf * 16 + g;
        #pragma unroll
        for (int nf = 0; nf < 4; nf++) {
            int col = colBlk + wn * 32 + nf * 8 + tg * 2;
            float vals[4] = {acc[mf][nf].x, acc[mf][nf].y, acc[mf][nf].z, acc[mf][nf].w};
            #pragma unroll
            for (int h = 0; h < 2; h++) {        // c0,c1 (row0) / c2,c3 (row0+8)
                int row = row0 + h * 8;
                #pragma unroll
                for (int e = 0; e < 2; e++) {
                    int c = col + e;
                    if (c < N) {
                        float v = vals[h * 2 + e];
                        if (bias) v += bias[c];
                        if (GELU) v = 0.5f * v * (1.0f + erff(v * 0.7071067811865476f));
                        if (res)  v += res[(size_t)row * N + c];
                        Cout[(size_t)row * N + c] = v;
                    }
                }
            }
        }
    }
}

// ---------------- attention: S = scale * Q Kt, causal blocks only ----------------
__global__ void attn_scores_kernel() {
    int bx = blockIdx.x;
    int by = blockIdx.y;
    if (bx > by) return;
    int bh = blockIdx.z;
    int b = bh / Hz, h = bh % Hz;
    __shared__ float sQ[64][65];
    __shared__ float sK[64][65];
    int tid = threadIdx.x;
    int lr = tid >> 4;
    int lc = (tid & 15) * 4;
    #pragma unroll
    for (int r = 0; r < 4; r++) {
        int row = lr + r * 16;
        float4 qv = *(const float4*)(g_q + (size_t)(b * Tz + by * 64 + row) * Cz + h * HDz + lc);
        sQ[row][lc] = qv.x; sQ[row][lc + 1] = qv.y; sQ[row][lc + 2] = qv.z; sQ[row][lc + 3] = qv.w;
        float4 kv = *(const float4*)(g_k + (size_t)(b * Tz + bx * 64 + row) * Cz + h * HDz + lc);
        sK[row][lc] = kv.x; sK[row][lc + 1] = kv.y; sK[row][lc + 2] = kv.z; sK[row][lc + 3] = kv.w;
    }
    __syncthreads();
    int tx = tid & 15, ty = tid >> 4;
    float acc[4][4] = {};
    #pragma unroll
    for (int d = 0; d < 64; d++) {
        float rm[4], rn[4];
        #pragma unroll
        for (int i = 0; i < 4; i++) rm[i] = sQ[ty * 4 + i][d];
        #pragma unroll
        for (int j = 0; j < 4; j++) rn[j] = sK[tx * 4 + j][d];
        #pragma unroll
        for (int i = 0; i < 4; i++)
            #pragma unroll
            for (int j = 0; j < 4; j++)
                acc[i][j] += rm[i] * rn[j];
    }
    const float scale = 0.125f;
    #pragma unroll
    for (int i = 0; i < 4; i++) {
        size_t base = ((size_t)bh * Tz + by * 64 + ty * 4 + i) * Tz + bx * 64 + tx * 4;
        #pragma unroll
        for (int j = 0; j < 4; j++)
            g_att[base + j] = acc[i][j] * scale;
    }
}

// ---------------- causal softmax ----------------
__global__ void softmax_kernel() {
    int m = blockIdx.x;
    int i = m % Tz;
    float* row = g_att + (size_t)m * Tz;
    int n = i + 1;
    int tid = threadIdx.x;
    float mx = -1e30f;
    for (int j = tid; j < n; j += 256) mx = fmaxf(mx, row[j]);
    mx = blockReduceMax(mx);
    float s = 0.f;
    for (int j = tid; j < n; j += 256) {
        float e = expf(row[j] - mx);
        row[j] = e;
        s += e;
    }
    s = blockReduceSum(s);
    float inv = 1.0f / s;
    for (int j = tid; j < n; j += 256) row[j] *= inv;
    for (int j = n + tid; j < Tz; j += 256) row[j] = 0.f;
}

// ---------------- Y = att @ V ----------------
__global__ void attn_av_kernel() {
    int by = blockIdx.x;
    int bh = blockIdx.y;
    int b = bh / Hz, h = bh % Hz;
    __shared__ float sA[64][65];
    __shared__ float sV[64][65];
    int tid = threadIdx.x;
    int lr = tid >> 4;
    int lc = (tid & 15) * 4;
    int tx = tid & 15, ty = tid >> 4;
    float acc[4][4] = {};
    for (int kt = 0; kt <= by; kt++) {
        #pragma unroll
        for (int r = 0; r < 4; r++) {
            int row = lr + r * 16;
            float4 av = *(const float4*)(g_att + ((size_t)bh * Tz + by * 64 + row) * Tz + kt * 64 + lc);
            sA[row][lc] = av.x; sA[row][lc + 1] = av.y; sA[row][lc + 2] = av.z; sA[row][lc + 3] = av.w;
            float4 vv = *(const float4*)(g_v + (size_t)(b * Tz + kt * 64 + row) * Cz + h * HDz + lc);
            sV[row][lc] = vv.x; sV[row][lc + 1] = vv.y; sV[row][lc + 2] = vv.z; sV[row][lc + 3] = vv.w;
        }
        __syncthreads();
        #pragma unroll
        for (int j = 0; j < 64; j++) {
            float rm[4], rn[4];
            #pragma unroll
            for (int i = 0; i < 4; i++) rm[i] = sA[ty * 4 + i][j];
            #pragma unroll
            for (int d = 0; d < 4; d++) rn[d] = sV[j][tx * 4 + d];
            #pragma unroll
            for (int i = 0; i < 4; i++)
                #pragma unroll
                for (int d = 0; d < 4; d++)
                    acc[i][d] += rm[i] * rn[d];
        }
        __syncthreads();
    }
    #pragma unroll
    for (int i = 0; i < 4; i++)
        #pragma unroll
        for (int d = 0; d < 4; d++)
            g_y[(size_t)(b * Tz + by * 64 + ty * 4 + i) * Cz + h * HDz + tx * 4 + d] = acc[i][d];
}

// ---------------- loss ----------------
__global__ void loss_row_kernel(const float* __restrict__ logits,
                                const int* __restrict__ targets) {
    int r = blockIdx.x;
    const float* row = logits + (size_t)r * Vz;
    int tid = threadIdx.x;
    float mx = -1e30f;
    for (int j = tid; j < Vz; j += 256) mx = fmaxf(mx, row[j]);
    mx = blockReduceMax(mx);
    float s = 0.f;
    for (int j = tid; j < Vz; j += 256) s += expf(row[j] - mx);
    s = blockReduceSum(s);
    if (tid == 0) {
        int t = targets[r];
        g_red[r] = -(row[t] - mx - logf(s));
    }
}

__global__ void loss_final_kernel(float* __restrict__ out, int out_size) {
    int tid = threadIdx.x;
    float s = 0.f;
    for (int j = tid; j < BTz; j += 256) s += g_red[j];
    s = blockReduceSum(s);
    if (tid == 0) {
        long long logits_elems = (long long)BTz * Vz;
        if ((long long)out_size > logits_elems)
            out[logits_elems] = s / (float)BTz;
    }
}

// ---------------- launch ----------------
#define MMA_SMEM (2 * MBM * MLDS * (int)sizeof(__nv_bfloat16))

extern "C" void kernel_launch(void* const* d_in, const int* in_sizes, int n_in,
                              void* d_out, int out_size) {
    const int*   idx     = (const int*)d_in[0];
    const int*   targets = (const int*)d_in[1];
    const float* tok_emb = (const float*)d_in[2];
    const float* pos_emb = (const float*)d_in[3];
    const float* ln1_w   = (const float*)d_in[4];
    const float* ln1_b   = (const float*)d_in[5];
    const float* ln2_w   = (const float*)d_in[6];
    const float* ln2_b   = (const float*)d_in[7];
    const float* Wq = (const float*)d_in[8];
    const float* bq = (const float*)d_in[9];
    const float* Wk = (const float*)d_in[10];
    const float* bk = (const float*)d_in[11];
    const float* Wv = (const float*)d_in[12];
    const float* bv = (const float*)d_in[13];
    const float* Wo = (const float*)d_in[14];
    const float* bo = (const float*)d_in[15];
    const float* W1 = (const float*)d_in[16];
    const float* b1 = (const float*)d_in[17];
    const float* W2 = (const float*)d_in[18];
    const float* b2 = (const float*)d_in[19];
    const float* lnf_w  = (const float*)d_in[20];
    const float* lnf_b  = (const float*)d_in[21];
    const float* head_w = (const float*)d_in[22];
    float* out = (float*)d_out;

    float *px, *ph, *pq, *pk, *pv, *py, *pff;
    cudaGetSymbolAddress((void**)&px,  g_x);
    cudaGetSymbolAddress((void**)&ph,  g_h);
    cudaGetSymbolAddress((void**)&pq,  g_q);
    cudaGetSymbolAddress((void**)&pk,  g_k);
    cudaGetSymbolAddress((void**)&pv,  g_v);
    cudaGetSymbolAddress((void**)&py,  g_y);
    cudaGetSymbolAddress((void**)&pff, g_ff);

    cudaFuncSetAttribute(gemm_mma_kernel<false, true>,
                         cudaFuncAttributeMaxDynamicSharedMemorySize, MMA_SMEM);
    cudaFuncSetAttribute(gemm_mma_kernel<true, true>,
                         cudaFuncAttributeMaxDynamicSharedMemorySize, MMA_SMEM);
    cudaFuncSetAttribute(gemm_mma_kernel<false, false>,
                         cudaFuncAttributeMaxDynamicSharedMemorySize, MMA_SMEM);

    embed_kernel<<<BTz, 256>>>(idx, tok_emb, pos_emb);

    const size_t CC  = (size_t)Cz * Cz;
    const size_t C14 = (size_t)Cz * C4z;
    dim3 gCC(Cz / MBN, BTz / MBM);     // 8 x 16
    dim3 gC4(C4z / MBN, BTz / MBM);    // 32 x 16
    dim3 gHead((Vz + MBN - 1) / MBN, BTz / MBM);

    for (int l = 0; l < Lz; l++) {
        ln_kernel<<<BTz, 256>>>(px, ln1_w + (size_t)l * Cz, ln1_b + (size_t)l * Cz, ph);
        gemm_mma_kernel<false, true><<<gCC, 256, MMA_SMEM>>>(ph, Wq + l * CC, bq + (size_t)l * Cz, nullptr, pq, BTz, Cz, Cz);
        gemm_mma_kernel<false, true><<<gCC, 256, MMA_SMEM>>>(ph, Wk + l * CC, bk + (size_t)l * Cz, nullptr, pk, BTz, Cz, Cz);
        gemm_mma_kernel<false, true><<<gCC, 256, MMA_SMEM>>>(ph, Wv + l * CC, bv + (size_t)l * Cz, nullptr, pv, BTz, Cz, Cz);
        attn_scores_kernel<<<dim3(16, 16, Bz * Hz), 256>>>();
        softmax_kernel<<<Bz * Hz * Tz, 256>>>();
        attn_av_kernel<<<dim3(16, Bz * Hz), 256>>>();
        gemm_mma_kernel<false, true><<<gCC, 256, MMA_SMEM>>>(py, Wo + l * CC, bo + (size_t)l * Cz, px, px, BTz, Cz, Cz);
        ln_kernel<<<BTz, 256>>>(px, ln2_w + (size_t)l * Cz, ln2_b + (size_t)l * Cz, ph);
        gemm_mma_kernel<true , true><<<gC4, 256, MMA_SMEM>>>(ph, W1 + l * C14, b1 + (size_t)l * C4z, nullptr, pff, BTz, C4z, Cz);
        gemm_mma_kernel<false, true><<<gCC, 256, MMA_SMEM>>>(pff, W2 + l * C14, b2 + (size_t)l * Cz, px, px, BTz, Cz, C4z);
    }

    ln_kernel<<<BTz, 256>>>(px, lnf_w, lnf_b, ph);
    gemm_mma_kernel<false, false><<<gHead, 256, MMA_SMEM>>>(ph, head_w, nullptr, nullptr, out, BTz, Vz, Cz);
    loss_row_kernel<<<BTz, 256>>>(out, targets);
    loss_final_kernel<<<1, 256>>>(out, out_size);
}

// round 5
// speedup vs baseline: 1.8106x; 1.2176x over previous
#include <cuda_runtime.h>
#include <cuda_bf16.h>
#include <math.h>
#include <stdint.h>

#define Bz 2
#define Tz 1024
#define Cz 1024
#define Hz 16
#define HDz 64
#define Lz 12
#define Vz 50257
#define BTz (Bz*Tz)
#define C4z (4*Cz)
#define C3z (3*Cz)

// ---------------- scratch (device globals; no allocation) ----------------
__device__ float g_x[BTz*Cz];
__device__ float g_h[BTz*Cz];
__device__ float g_qkv[(size_t)BTz*C3z];
__device__ float g_y[BTz*Cz];
__device__ float g_ff[(size_t)BTz*C4z];
__device__ float g_att[(size_t)Bz*Hz*Tz*Tz];
__device__ float g_red[BTz];
__device__ float g_wpack[(size_t)Cz*C3z];
__device__ float g_bpack[C3z];

// ---------------- block reductions ----------------
__device__ __forceinline__ float blockReduceSum(float v) {
    __shared__ float sh[33];
    int lane = threadIdx.x & 31, w = threadIdx.x >> 5;
    #pragma unroll
    for (int o = 16; o; o >>= 1) v += __shfl_down_sync(0xffffffffu, v, o);
    __syncthreads();
    if (lane == 0) sh[w] = v;
    __syncthreads();
    if (threadIdx.x == 0) {
        float s = 0.f;
        int nw = blockDim.x >> 5;
        for (int i = 0; i < nw; i++) s += sh[i];
        sh[32] = s;
    }
    __syncthreads();
    return sh[32];
}

__device__ __forceinline__ float blockReduceMax(float v) {
    __shared__ float sh[33];
    int lane = threadIdx.x & 31, w = threadIdx.x >> 5;
    #pragma unroll
    for (int o = 16; o; o >>= 1) v = fmaxf(v, __shfl_down_sync(0xffffffffu, v, o));
    __syncthreads();
    if (lane == 0) sh[w] = v;
    __syncthreads();
    if (threadIdx.x == 0) {
        float s = -1e30f;
        int nw = blockDim.x >> 5;
        for (int i = 0; i < nw; i++) s = fmaxf(s, sh[i]);
        sh[32] = s;
    }
    __syncthreads();
    return sh[32];
}

// ---------------- embedding ----------------
__global__ void embed_kernel(const int* __restrict__ idx,
                             const float* __restrict__ tok,
                             const float* __restrict__ pos) {
    int r = blockIdx.x;
    int c = threadIdx.x * 4;
    int tokid = idx[r];
    float4 te = *(const float4*)(tok + (size_t)tokid * Cz + c);
    float4 pe = *(const float4*)(pos + (size_t)(r % Tz) * Cz + c);
    float4 o;
    o.x = te.x + pe.x; o.y = te.y + pe.y; o.z = te.z + pe.z; o.w = te.w + pe.w;
    *(float4*)(g_x + (size_t)r * Cz + c) = o;
}

// ---------------- layernorm ----------------
__global__ void ln_kernel(const float* __restrict__ x,
                          const float* __restrict__ w,
                          const float* __restrict__ b,
                          float* __restrict__ out) {
    int r = blockIdx.x;
    const float* xr = x + (size_t)r * Cz;
    float v[4];
    #pragma unroll
    for (int k = 0; k < 4; k++) v[k] = xr[threadIdx.x + k * 256];
    float s = v[0] + v[1] + v[2] + v[3];
    s = blockReduceSum(s);
    float mu = s * (1.0f / Cz);
    float sq = 0.f;
    #pragma unroll
    for (int k = 0; k < 4; k++) { float d = v[k] - mu; sq += d * d; }
    sq = blockReduceSum(sq);
    float rstd = rsqrtf(sq * (1.0f / Cz) + 1e-5f);
    float* orow = out + (size_t)r * Cz;
    #pragma unroll
    for (int k = 0; k < 4; k++) {
        int c = threadIdx.x + k * 256;
        orow[c] = (v[k] - mu) * rstd * w[c] + b[c];
    }
}

// ---------------- QKV weight/bias packing ----------------
__global__ void pack_w_kernel(const float* __restrict__ Wq,
                              const float* __restrict__ Wk,
                              const float* __restrict__ Wv) {
    int which = blockIdx.y;
    const float* src = (which == 0) ? Wq : (which == 1) ? Wk : Wv;
    int k = blockIdx.x;
    int c = threadIdx.x * 4;
    float4 v = *(const float4*)(src + (size_t)k * Cz + c);
    *(float4*)(g_wpack + (size_t)k * C3z + which * Cz + c) = v;
}

__global__ void pack_b_kernel(const float* __restrict__ bq,
                              const float* __restrict__ bk,
                              const float* __restrict__ bv) {
    int which = blockIdx.x;
    const float* src = (which == 0) ? bq : (which == 1) ? bk : bv;
    int c = threadIdx.x * 4;
    float4 v = *(const float4*)(src + c);
    *(float4*)(g_bpack + which * Cz + c) = v;
}

// =========================================================================
// Tensor-core GEMM (hi/lo bf16 split, K expanded 3x), 128x128 tile,
// ldmatrix fragment loads, double-buffered SMEM pipeline.
// SMEM row stride 104 bf16 = 13 x 16B chunks (odd -> conflict-free ldmatrix).
// =========================================================================
#define MST 104
#define ATILE (128*MST)          // bf16 elems per tile buffer
#define TILEB (ATILE*2)          // bytes per tile buffer
#define GSMEM (4*TILEB)          // A0,B0,A1,B1

__device__ __forceinline__ void mma16816(float4& c, uint32_t a0, uint32_t a1,
                                         uint32_t a2, uint32_t a3,
                                         uint32_t b0, uint32_t b1) {
    asm volatile(
        "mma.sync.aligned.m16n8k16.row.col.f32.bf16.bf16.f32 "
        "{%0,%1,%2,%3}, {%4,%5,%6,%7}, {%8,%9}, {%0,%1,%2,%3};"
        : "+f"(c.x), "+f"(c.y), "+f"(c.z), "+f"(c.w)
        : "r"(a0), "r"(a1), "r"(a2), "r"(a3), "r"(b0), "r"(b1));
}

__device__ __forceinline__ void ldsm4(uint32_t& r0, uint32_t& r1,
                                      uint32_t& r2, uint32_t& r3, uint32_t addr) {
    asm volatile("ldmatrix.sync.aligned.m8n8.x4.shared.b16 {%0,%1,%2,%3}, [%4];"
        : "=r"(r0), "=r"(r1), "=r"(r2), "=r"(r3) : "r"(addr));
}

template<bool GELU, bool NGUARD>
__global__ void __launch_bounds__(256, 1)
gemm_mma_kernel(const float* __restrict__ A, const float* __restrict__ Bm,
                const float* __restrict__ bias, const float* __restrict__ res,
                float* __restrict__ Cout, int M, int N, int K) {
    extern __shared__ __nv_bfloat16 smem[];
    int tid = threadIdx.x, lane = tid & 31, warp = tid >> 5;
    int wm = warp & 1, wn = warp >> 1;
    int g = lane >> 2, tg = lane & 3;
    int rowBlk = blockIdx.y * 128, colBlk = blockIdx.x * 128;

    // staging thread mapping
    int arow = tid >> 1, aseg = tid & 1;          // A: 128 rows x 2 k-segs
    int bn = tid & 127, bseg = tid >> 7;          // B: 128 cols x 2 k-segs

    // ldmatrix per-lane offsets (bf16 units)
    int t8 = lane >> 3, r8 = lane & 7;
    int aoff = ((t8 & 1) * 8 + r8) * MST + (t8 >> 1) * 8;
    int boff = ((t8 >> 1) * 8 + r8) * MST + (t8 & 1) * 8;

    uint32_t sbase = (uint32_t)__cvta_generic_to_shared(smem);

    const float* aPtr = A + (size_t)(rowBlk + arow) * K + aseg * 16;
    int nb = colBlk + bn;
    bool bValid = (!NGUARD) || (nb < N);
    const float* bPtr = Bm + (size_t)bseg * 16 * N + (bValid ? nb : 0);

    float4 fa[4];
    float fb[16];
    float4 acc[4][4];
    #pragma unroll
    for (int i = 0; i < 4; i++)
        #pragma unroll
        for (int j = 0; j < 4; j++) acc[i][j] = make_float4(0.f, 0.f, 0.f, 0.f);

#define LDGA(kt) { const float* p = aPtr + (kt) * 32; \
        fa[0] = *(const float4*)(p); fa[1] = *(const float4*)(p + 4); \
        fa[2] = *(const float4*)(p + 8); fa[3] = *(const float4*)(p + 12); }

#define LDGB(kt) { const float* p = bPtr + (size_t)(kt) * 32 * N; \
        _Pragma("unroll") \
        for (int i = 0; i < 16; i++) fb[i] = (!NGUARD || bValid) ? p[(size_t)i * N] : 0.f; }

#define CVTA(s) { __nv_bfloat16* As_ = smem + (s) * (2 * ATILE); \
        uint32_t w_[16]; unsigned short hs_[16]; \
        const float* fap = (const float*)fa; \
        _Pragma("unroll") \
        for (int i = 0; i < 16; i++) { \
            float x = fap[i]; \
            __nv_bfloat16 h = __float2bfloat16(x); \
            unsigned short hb = __bfloat16_as_ushort(h); \
            __nv_bfloat16 lo = __float2bfloat16(x - __bfloat162float(h)); \
            w_[i] = (uint32_t)hb | ((uint32_t)__bfloat16_as_ushort(lo) << 16); \
            hs_[i] = hb; } \
        uint4* d0 = (uint4*)(As_ + arow * MST + aseg * 32); \
        const uint4* wv_ = (const uint4*)w_; \
        d0[0] = wv_[0]; d0[1] = wv_[1]; d0[2] = wv_[2]; d0[3] = wv_[3]; \
        uint32_t hw_[8]; \
        _Pragma("unroll") \
        for (int j = 0; j < 8; j++) hw_[j] = (uint32_t)hs_[2*j] | ((uint32_t)hs_[2*j+1] << 16); \
        uint4* d1 = (uint4*)(As_ + arow * MST + 64 + aseg * 16); \
        d1[0] = ((const uint4*)hw_)[0]; d1[1] = ((const uint4*)hw_)[1]; }

#define CVTB(s) { __nv_bfloat16* Bs_ = smem + ATILE + (s) * (2 * ATILE); \
        uint32_t w_[16]; unsigned short ls_[16]; \
        _Pragma("unroll") \
        for (int i = 0; i < 16; i++) { \
            float x = fb[i]; \
            __nv_bfloat16 h = __float2bfloat16(x); \
            unsigned short hb = __bfloat16_as_ushort(h); \
            __nv_bfloat16 lo = __float2bfloat16(x - __bfloat162float(h)); \
            w_[i] = (uint32_t)hb | ((uint32_t)hb << 16); \
            ls_[i] = __bfloat16_as_ushort(lo); } \
        uint4* d0 = (uint4*)(Bs_ + bn * MST + bseg * 32); \
        const uint4* wv_ = (const uint4*)w_; \
        d0[0] = wv_[0]; d0[1] = wv_[1]; d0[2] = wv_[2]; d0[3] = wv_[3]; \
        uint32_t lw_[8]; \
        _Pragma("unroll") \
        for (int j = 0; j < 8; j++) lw_[j] = (uint32_t)ls_[2*j] | ((uint32_t)ls_[2*j+1] << 16); \
        uint4* d1 = (uint4*)(Bs_ + bn * MST + 64 + bseg * 16); \
        d1[0] = ((const uint4*)lw_)[0]; d1[1] = ((const uint4*)lw_)[1]; }

#define MMAS(s) { uint32_t Ab = sbase + (s) * (2 * TILEB); \
        uint32_t Bb = sbase + TILEB + (s) * (2 * TILEB); \
        _Pragma("unroll") \
        for (int ks = 0; ks < 6; ks++) { \
            int kb = ks * 16; \
            uint32_t ra[4][4], rb[4][2]; \
            _Pragma("unroll") \
            for (int mf = 0; mf < 4; mf++) \
                ldsm4(ra[mf][0], ra[mf][1], ra[mf][2], ra[mf][3], \
                      Ab + 2u * (uint32_t)((wm * 64 + mf * 16) * MST + aoff + kb)); \
            _Pragma("unroll") \
            for (int p = 0; p < 2; p++) \
                ldsm4(rb[2*p][0], rb[2*p][1], rb[2*p+1][0], rb[2*p+1][1], \
                      Bb + 2u * (uint32_t)((wn * 32 + p * 16) * MST + boff + kb)); \
            _Pragma("unroll") \
            for (int mf = 0; mf < 4; mf++) \
                _Pragma("unroll") \
                for (int nf = 0; nf < 4; nf++) \
                    mma16816(acc[mf][nf], ra[mf][0], ra[mf][1], ra[mf][2], ra[mf][3], \
                             rb[nf][0], rb[nf][1]); } }

    int nt = K / 32;
    LDGA(0); LDGB(0);
    CVTA(0); CVTB(0);
    for (int kt = 0; kt < nt; kt++) {
        int s = kt & 1;
        if (kt + 1 < nt) { LDGA(kt + 1); LDGB(kt + 1); }
        __syncthreads();
        MMAS(s);
        if (kt + 1 < nt) { CVTA(s ^ 1); CVTB(s ^ 1); }
    }

    // ---- epilogue ----
    #pragma unroll
    for (int mf = 0; mf < 4; mf++) {
        int row0 = rowBlk + wm * 64 + mf * 16 + g;
        #pragma unroll
        for (int nf = 0; nf < 4; nf++) {
            int col = colBlk + wn * 32 + nf * 8 + tg * 2;
            float vals[4] = {acc[mf][nf].x, acc[mf][nf].y, acc[mf][nf].z, acc[mf][nf].w};
            #pragma unroll
            for (int h = 0; h < 2; h++) {
                int row = row0 + h * 8;
                #pragma unroll
                for (int e = 0; e < 2; e++) {
                    int c = col + e;
                    if (!NGUARD || c < N) {
                        float v = vals[h * 2 + e];
                        if (bias) v += bias[c];
                        if (GELU) v = 0.5f * v * (1.0f + erff(v * 0.7071067811865476f));
                        if (res)  v += res[(size_t)row * N + c];
                        Cout[(size_t)row * N + c] = v;
                    }
                }
            }
        }
    }
#undef LDGA
#undef LDGB
#undef CVTA
#undef CVTB
#undef MMAS
}

// ---------------- attention: S = scale * Q Kt, causal blocks only ----------------
__global__ void attn_scores_kernel() {
    int bx = blockIdx.x;
    int by = blockIdx.y;
    if (bx > by) return;
    int bh = blockIdx.z;
    int b = bh / Hz, h = bh % Hz;
    __shared__ float sQ[64][65];
    __shared__ float sK[64][65];
    int tid = threadIdx.x;
    int lr = tid >> 4;
    int lc = (tid & 15) * 4;
    #pragma unroll
    for (int r = 0; r < 4; r++) {
        int row = lr + r * 16;
        float4 qv = *(const float4*)(g_qkv + (size_t)(b * Tz + by * 64 + row) * C3z + h * HDz + lc);
        sQ[row][lc] = qv.x; sQ[row][lc + 1] = qv.y; sQ[row][lc + 2] = qv.z; sQ[row][lc + 3] = qv.w;
        float4 kv = *(const float4*)(g_qkv + (size_t)(b * Tz + bx * 64 + row) * C3z + Cz + h * HDz + lc);
        sK[row][lc] = kv.x; sK[row][lc + 1] = kv.y; sK[row][lc + 2] = kv.z; sK[row][lc + 3] = kv.w;
    }
    __syncthreads();
    int tx = tid & 15, ty = tid >> 4;
    float acc[4][4] = {};
    #pragma unroll
    for (int d = 0; d < 64; d++) {
        float rm[4], rn[4];
        #pragma unroll
        for (int i = 0; i < 4; i++) rm[i] = sQ[ty * 4 + i][d];
        #pragma unroll
        for (int j = 0; j < 4; j++) rn[j] = sK[tx * 4 + j][d];
        #pragma unroll
        for (int i = 0; i < 4; i++)
            #pragma unroll
            for (int j = 0; j < 4; j++)
                acc[i][j] += rm[i] * rn[j];
    }
    const float scale = 0.125f;
    #pragma unroll
    for (int i = 0; i < 4; i++) {
        size_t base = ((size_t)bh * Tz + by * 64 + ty * 4 + i) * Tz + bx * 64 + tx * 4;
        #pragma unroll
        for (int j = 0; j < 4; j++)
            g_att[base + j] = acc[i][j] * scale;
    }
}

// ---------------- causal softmax ----------------
__global__ void softmax_kernel() {
    int m = blockIdx.x;
    int i = m % Tz;
    float* row = g_att + (size_t)m * Tz;
    int n = i + 1;
    int tid = threadIdx.x;
    float mx = -1e30f;
    for (int j = tid; j < n; j += 256) mx = fmaxf(mx, row[j]);
    mx = blockReduceMax(mx);
    float s = 0.f;
    for (int j = tid; j < n; j += 256) {
        float e = expf(row[j] - mx);
        row[j] = e;
        s += e;
    }
    s = blockReduceSum(s);
    float inv = 1.0f / s;
    for (int j = tid; j < n; j += 256) row[j] *= inv;
    for (int j = n + tid; j < Tz; j += 256) row[j] = 0.f;
}

// ---------------- Y = att @ V ----------------
__global__ void attn_av_kernel() {
    int by = blockIdx.x;
    int bh = blockIdx.y;
    int b = bh / Hz, h = bh % Hz;
    __shared__ float sA[64][65];
    __shared__ float sV[64][65];
    int tid = threadIdx.x;
    int lr = tid >> 4;
    int lc = (tid & 15) * 4;
    int tx = tid & 15, ty = tid >> 4;
    float acc[4][4] = {};
    for (int kt = 0; kt <= by; kt++) {
        #pragma unroll
        for (int r = 0; r < 4; r++) {
            int row = lr + r * 16;
            float4 av = *(const float4*)(g_att + ((size_t)bh * Tz + by * 64 + row) * Tz + kt * 64 + lc);
            sA[row][lc] = av.x; sA[row][lc + 1] = av.y; sA[row][lc + 2] = av.z; sA[row][lc + 3] = av.w;
            float4 vv = *(const float4*)(g_qkv + (size_t)(b * Tz + kt * 64 + row) * C3z + 2 * Cz + h * HDz + lc);
            sV[row][lc] = vv.x; sV[row][lc + 1] = vv.y; sV[row][lc + 2] = vv.z; sV[row][lc + 3] = vv.w;
        }
        __syncthreads();
        #pragma unroll
        for (int j = 0; j < 64; j++) {
            float rm[4], rn[4];
            #pragma unroll
            for (int i = 0; i < 4; i++) rm[i] = sA[ty * 4 + i][j];
            #pragma unroll
            for (int d = 0; d < 4; d++) rn[d] = sV[j][tx * 4 + d];
            #pragma unroll
            for (int i = 0; i < 4; i++)
                #pragma unroll
                for (int d = 0; d < 4; d++)
                    acc[i][d] += rm[i] * rn[d];
        }
        __syncthreads();
    }
    #pragma unroll
    for (int i = 0; i < 4; i++)
        #pragma unroll
        for (int d = 0; d < 4; d++)
            g_y[(size_t)(b * Tz + by * 64 + ty * 4 + i) * Cz + h * HDz + tx * 4 + d] = acc[i][d];
}

// ---------------- loss ----------------
__global__ void loss_row_kernel(const float* __restrict__ logits,
                                const int* __restrict__ targets) {
    int r = blockIdx.x;
    const float* row = logits + (size_t)r * Vz;
    int tid = threadIdx.x;
    float mx = -1e30f;
    for (int j = tid; j < Vz; j += 256) mx = fmaxf(mx, row[j]);
    mx = blockReduceMax(mx);
    float s = 0.f;
    for (int j = tid; j < Vz; j += 256) s += expf(row[j] - mx);
    s = blockReduceSum(s);
    if (tid == 0) {
        int t = targets[r];
        g_red[r] = -(row[t] - mx - logf(s));
    }
}

__global__ void loss_final_kernel(float* __restrict__ out, int out_size) {
    int tid = threadIdx.x;
    float s = 0.f;
    for (int j = tid; j < BTz; j += 256) s += g_red[j];
    s = blockReduceSum(s);
    if (tid == 0) {
        long long logits_elems = (long long)BTz * Vz;
        if ((long long)out_size > logits_elems)
            out[logits_elems] = s / (float)BTz;
    }
}

// ---------------- launch ----------------
extern "C" void kernel_launch(void* const* d_in, const int* in_sizes, int n_in,
                              void* d_out, int out_size) {
    const int*   idx     = (const int*)d_in[0];
    const int*   targets = (const int*)d_in[1];
    const float* tok_emb = (const float*)d_in[2];
    const float* pos_emb = (const float*)d_in[3];
    const float* ln1_w   = (const float*)d_in[4];
    const float* ln1_b   = (const float*)d_in[5];
    const float* ln2_w   = (const float*)d_in[6];
    const float* ln2_b   = (const float*)d_in[7];
    const float* Wq = (const float*)d_in[8];
    const float* bq = (const float*)d_in[9];
    const float* Wk = (const float*)d_in[10];
    const float* bk = (const float*)d_in[11];
    const float* Wv = (const float*)d_in[12];
    const float* bv = (const float*)d_in[13];
    const float* Wo = (const float*)d_in[14];
    const float* bo = (const float*)d_in[15];
    const float* W1 = (const float*)d_in[16];
    const float* b1 = (const float*)d_in[17];
    const float* W2 = (const float*)d_in[18];
    const float* b2 = (const float*)d_in[19];
    const float* lnf_w  = (const float*)d_in[20];
    const float* lnf_b  = (const float*)d_in[21];
    const float* head_w = (const float*)d_in[22];
    float* out = (float*)d_out;

    float *px, *ph, *pqkv, *py, *pff, *pwp, *pbp;
    cudaGetSymbolAddress((void**)&px,   g_x);
    cudaGetSymbolAddress((void**)&ph,   g_h);
    cudaGetSymbolAddress((void**)&pqkv, g_qkv);
    cudaGetSymbolAddress((void**)&py,   g_y);
    cudaGetSymbolAddress((void**)&pff,  g_ff);
    cudaGetSymbolAddress((void**)&pwp,  g_wpack);
    cudaGetSymbolAddress((void**)&pbp,  g_bpack);

    cudaFuncSetAttribute(gemm_mma_kernel<false, false>,
                         cudaFuncAttributeMaxDynamicSharedMemorySize, GSMEM);
    cudaFuncSetAttribute(gemm_mma_kernel<true, false>,
                         cudaFuncAttributeMaxDynamicSharedMemorySize, GSMEM);
    cudaFuncSetAttribute(gemm_mma_kernel<false, true>,
                         cudaFuncAttributeMaxDynamicSharedMemorySize, GSMEM);

    embed_kernel<<<BTz, 256>>>(idx, tok_emb, pos_emb);

    const size_t CC  = (size_t)Cz * Cz;
    const size_t C14 = (size_t)Cz * C4z;
    dim3 gQKV(C3z / 128, BTz / 128);   // 24 x 16
    dim3 gCC(Cz / 128, BTz / 128);     // 8 x 16
    dim3 gC4(C4z / 128, BTz / 128);    // 32 x 16
    dim3 gHead((Vz + 127) / 128, BTz / 128);

    for (int l = 0; l < Lz; l++) {
        pack_w_kernel<<<dim3(Cz, 3), 256>>>(Wq + l * CC, Wk + l * CC, Wv + l * CC);
        pack_b_kernel<<<3, 256>>>(bq + (size_t)l * Cz, bk + (size_t)l * Cz, bv + (size_t)l * Cz);
        ln_kernel<<<BTz, 256>>>(px, ln1_w + (size_t)l * Cz, ln1_b + (size_t)l * Cz, ph);
        gemm_mma_kernel<false, false><<<gQKV, 256, GSMEM>>>(ph, pwp, pbp, nullptr, pqkv, BTz, C3z, Cz);
        attn_scores_kernel<<<dim3(16, 16, Bz * Hz), 256>>>();
        softmax_kernel<<<Bz * Hz * Tz, 256>>>();
        attn_av_kernel<<<dim3(16, Bz * Hz), 256>>>();
        gemm_mma_kernel<false, false><<<gCC, 256, GSMEM>>>(py, Wo + l * CC, bo + (size_t)l * Cz, px, px, BTz, Cz, Cz);
        ln_kernel<<<BTz, 256>>>(px, ln2_w + (size_t)l * Cz, ln2_b + (size_t)l * Cz, ph);
        gemm_mma_kernel<true , false><<<gC4, 256, GSMEM>>>(ph, W1 + l * C14, b1 + (size_t)l * C4z, nullptr, pff, BTz, C4z, Cz);
        gemm_mma_kernel<false, false><<<gCC, 256, GSMEM>>>(pff, W2 + l * C14, b2 + (size_t)l * Cz, px, px, BTz, Cz, C4z);
    }

    ln_kernel<<<BTz, 256>>>(px, lnf_w, lnf_b, ph);
    gemm_mma_kernel<false, true><<<gHead, 256, GSMEM>>>(ph, head_w, nullptr, nullptr, out, BTz, Vz, Cz);
    loss_row_kernel<<<BTz, 256>>>(out, targets);
    loss_final_kernel<<<1, 256>>>(out, out_size);
}

// round 6
// speedup vs baseline: 2.1528x; 1.1890x over previous
#include <cuda_runtime.h>
#include <cuda_bf16.h>
#include <math.h>
#include <stdint.h>

#define Bz 2
#define Tz 1024
#define Cz 1024
#define Hz 16
#define HDz 64
#define Lz 12
#define Vz 50257
#define BTz (Bz*Tz)
#define C4z (4*Cz)
#define C3z (3*Cz)

// ---------------- scratch (device globals; no allocation) ----------------
__device__ float g_x[BTz*Cz];
__device__ float g_h[BTz*Cz];
__device__ float g_qkv[(size_t)BTz*C3z];
__device__ float g_y[BTz*Cz];
__device__ float g_ff[(size_t)BTz*C4z];
__device__ float g_red[BTz];
__device__ float g_wpack[(size_t)Cz*C3z];
__device__ float g_bpack[C3z];

// ---------------- block reductions ----------------
__device__ __forceinline__ float blockReduceSum(float v) {
    __shared__ float sh[33];
    int lane = threadIdx.x & 31, w = threadIdx.x >> 5;
    #pragma unroll
    for (int o = 16; o; o >>= 1) v += __shfl_down_sync(0xffffffffu, v, o);
    __syncthreads();
    if (lane == 0) sh[w] = v;
    __syncthreads();
    if (threadIdx.x == 0) {
        float s = 0.f;
        int nw = blockDim.x >> 5;
        for (int i = 0; i < nw; i++) s += sh[i];
        sh[32] = s;
    }
    __syncthreads();
    return sh[32];
}

__device__ __forceinline__ float blockReduceMax(float v) {
    __shared__ float sh[33];
    int lane = threadIdx.x & 31, w = threadIdx.x >> 5;
    #pragma unroll
    for (int o = 16; o; o >>= 1) v = fmaxf(v, __shfl_down_sync(0xffffffffu, v, o));
    __syncthreads();
    if (lane == 0) sh[w] = v;
    __syncthreads();
    if (threadIdx.x == 0) {
        float s = -1e30f;
        int nw = blockDim.x >> 5;
        for (int i = 0; i < nw; i++) s = fmaxf(s, sh[i]);
        sh[32] = s;
    }
    __syncthreads();
    return sh[32];
}

// ---------------- embedding ----------------
__global__ void embed_kernel(const int* __restrict__ idx,
                             const float* __restrict__ tok,
                             const float* __restrict__ pos) {
    int r = blockIdx.x;
    int c = threadIdx.x * 4;
    int tokid = idx[r];
    float4 te = *(const float4*)(tok + (size_t)tokid * Cz + c);
    float4 pe = *(const float4*)(pos + (size_t)(r % Tz) * Cz + c);
    float4 o;
    o.x = te.x + pe.x; o.y = te.y + pe.y; o.z = te.z + pe.z; o.w = te.w + pe.w;
    *(float4*)(g_x + (size_t)r * Cz + c) = o;
}

// ---------------- layernorm ----------------
__global__ void ln_kernel(const float* __restrict__ x,
                          const float* __restrict__ w,
                          const float* __restrict__ b,
                          float* __restrict__ out) {
    int r = blockIdx.x;
    const float* xr = x + (size_t)r * Cz;
    float v[4];
    #pragma unroll
    for (int k = 0; k < 4; k++) v[k] = xr[threadIdx.x + k * 256];
    float s = v[0] + v[1] + v[2] + v[3];
    s = blockReduceSum(s);
    float mu = s * (1.0f / Cz);
    float sq = 0.f;
    #pragma unroll
    for (int k = 0; k < 4; k++) { float d = v[k] - mu; sq += d * d; }
    sq = blockReduceSum(sq);
    float rstd = rsqrtf(sq * (1.0f / Cz) + 1e-5f);
    float* orow = out + (size_t)r * Cz;
    #pragma unroll
    for (int k = 0; k < 4; k++) {
        int c = threadIdx.x + k * 256;
        orow[c] = (v[k] - mu) * rstd * w[c] + b[c];
    }
}

// ---------------- QKV weight/bias packing ----------------
__global__ void pack_w_kernel(const float* __restrict__ Wq,
                              const float* __restrict__ Wk,
                              const float* __restrict__ Wv) {
    int which = blockIdx.y;
    const float* src = (which == 0) ? Wq : (which == 1) ? Wk : Wv;
    int k = blockIdx.x;
    int c = threadIdx.x * 4;
    float4 v = *(const float4*)(src + (size_t)k * Cz + c);
    *(float4*)(g_wpack + (size_t)k * C3z + which * Cz + c) = v;
}

__global__ void pack_b_kernel(const float* __restrict__ bq,
                              const float* __restrict__ bk,
                              const float* __restrict__ bv) {
    int which = blockIdx.x;
    const float* src = (which == 0) ? bq : (which == 1) ? bk : bv;
    int c = threadIdx.x * 4;
    float4 v = *(const float4*)(src + c);
    *(float4*)(g_bpack + which * Cz + c) = v;
}

// ---------------- mma / ldmatrix primitives ----------------
__device__ __forceinline__ void mma16816(float4& c, uint32_t a0, uint32_t a1,
                                         uint32_t a2, uint32_t a3,
                                         uint32_t b0, uint32_t b1) {
    asm volatile(
        "mma.sync.aligned.m16n8k16.row.col.f32.bf16.bf16.f32 "
        "{%0,%1,%2,%3}, {%4,%5,%6,%7}, {%8,%9}, {%0,%1,%2,%3};"
        : "+f"(c.x), "+f"(c.y), "+f"(c.z), "+f"(c.w)
        : "r"(a0), "r"(a1), "r"(a2), "r"(a3), "r"(b0), "r"(b1));
}

__device__ __forceinline__ void ldsm4(uint32_t& r0, uint32_t& r1,
                                      uint32_t& r2, uint32_t& r3, uint32_t addr) {
    asm volatile("ldmatrix.sync.aligned.m8n8.x4.shared.b16 {%0,%1,%2,%3}, [%4];"
        : "=r"(r0), "=r"(r1), "=r"(r2), "=r"(r3) : "r"(addr));
}

__device__ __forceinline__ uint32_t packbf(float x, float y) {
    return (uint32_t)__bfloat16_as_ushort(__float2bfloat16(x)) |
           ((uint32_t)__bfloat16_as_ushort(__float2bfloat16(y)) << 16);
}

// =========================================================================
// Tensor-core GEMM (hi/lo bf16 split, K expanded 3x), 128x128 tile,
// ldmatrix fragment loads, double-buffered SMEM pipeline.
// =========================================================================
#define MST 104
#define ATILE (128*MST)
#define TILEB (ATILE*2)
#define GSMEM (4*TILEB)

template<bool GELU, bool NGUARD>
__global__ void __launch_bounds__(256, 1)
gemm_mma_kernel(const float* __restrict__ A, const float* __restrict__ Bm,
                const float* __restrict__ bias, const float* __restrict__ res,
                float* __restrict__ Cout, int M, int N, int K) {
    extern __shared__ __nv_bfloat16 smem[];
    int tid = threadIdx.x, lane = tid & 31, warp = tid >> 5;
    int wm = warp & 1, wn = warp >> 1;
    int g = lane >> 2, tg = lane & 3;
    int rowBlk = blockIdx.y * 128, colBlk = blockIdx.x * 128;

    int arow = tid >> 1, aseg = tid & 1;
    int bn = tid & 127, bseg = tid >> 7;

    int t8 = lane >> 3, r8 = lane & 7;
    int aoff = ((t8 & 1) * 8 + r8) * MST + (t8 >> 1) * 8;
    int boff = ((t8 >> 1) * 8 + r8) * MST + (t8 & 1) * 8;

    uint32_t sbase = (uint32_t)__cvta_generic_to_shared(smem);

    const float* aPtr = A + (size_t)(rowBlk + arow) * K + aseg * 16;
    int nb = colBlk + bn;
    bool bValid = (!NGUARD) || (nb < N);
    const float* bPtr = Bm + (size_t)bseg * 16 * N + (bValid ? nb : 0);

    float4 fa[4];
    float fb[16];
    float4 acc[4][4];
    #pragma unroll
    for (int i = 0; i < 4; i++)
        #pragma unroll
        for (int j = 0; j < 4; j++) acc[i][j] = make_float4(0.f, 0.f, 0.f, 0.f);

#define LDGA(kt) { const float* p = aPtr + (kt) * 32; \
        fa[0] = *(const float4*)(p); fa[1] = *(const float4*)(p + 4); \
        fa[2] = *(const float4*)(p + 8); fa[3] = *(const float4*)(p + 12); }

#define LDGB(kt) { const float* p = bPtr + (size_t)(kt) * 32 * N; \
        _Pragma("unroll") \
        for (int i = 0; i < 16; i++) fb[i] = (!NGUARD || bValid) ? p[(size_t)i * N] : 0.f; }

#define CVTA(s) { __nv_bfloat16* As_ = smem + (s) * (2 * ATILE); \
        uint32_t w_[16]; unsigned short hs_[16]; \
        const float* fap = (const float*)fa; \
        _Pragma("unroll") \
        for (int i = 0; i < 16; i++) { \
            float x = fap[i]; \
            __nv_bfloat16 h = __float2bfloat16(x); \
            unsigned short hb = __bfloat16_as_ushort(h); \
            __nv_bfloat16 lo = __float2bfloat16(x - __bfloat162float(h)); \
            w_[i] = (uint32_t)hb | ((uint32_t)__bfloat16_as_ushort(lo) << 16); \
            hs_[i] = hb; } \
        uint4* d0 = (uint4*)(As_ + arow * MST + aseg * 32); \
        const uint4* wv_ = (const uint4*)w_; \
        d0[0] = wv_[0]; d0[1] = wv_[1]; d0[2] = wv_[2]; d0[3] = wv_[3]; \
        uint32_t hw_[8]; \
        _Pragma("unroll") \
        for (int j = 0; j < 8; j++) hw_[j] = (uint32_t)hs_[2*j] | ((uint32_t)hs_[2*j+1] << 16); \
        uint4* d1 = (uint4*)(As_ + arow * MST + 64 + aseg * 16); \
        d1[0] = ((const uint4*)hw_)[0]; d1[1] = ((const uint4*)hw_)[1]; }

#define CVTB(s) { __nv_bfloat16* Bs_ = smem + ATILE + (s) * (2 * ATILE); \
        uint32_t w_[16]; unsigned short ls_[16]; \
        _Pragma("unroll") \
        for (int i = 0; i < 16; i++) { \
            float x = fb[i]; \
            __nv_bfloat16 h = __float2bfloat16(x); \
            unsigned short hb = __bfloat16_as_ushort(h); \
            __nv_bfloat16 lo = __float2bfloat16(x - __bfloat162float(h)); \
            w_[i] = (uint32_t)hb | ((uint32_t)hb << 16); \
            ls_[i] = __bfloat16_as_ushort(lo); } \
        uint4* d0 = (uint4*)(Bs_ + bn * MST + bseg * 32); \
        const uint4* wv_ = (const uint4*)w_; \
        d0[0] = wv_[0]; d0[1] = wv_[1]; d0[2] = wv_[2]; d0[3] = wv_[3]; \
        uint32_t lw_[8]; \
        _Pragma("unroll") \
        for (int j = 0; j < 8; j++) lw_[j] = (uint32_t)ls_[2*j] | ((uint32_t)ls_[2*j+1] << 16); \
        uint4* d1 = (uint4*)(Bs_ + bn * MST + 64 + bseg * 16); \
        d1[0] = ((const uint4*)lw_)[0]; d1[1] = ((const uint4*)lw_)[1]; }

#define MMAS(s) { uint32_t Ab = sbase + (s) * (2 * TILEB); \
        uint32_t Bb = sbase + TILEB + (s) * (2 * TILEB); \
        _Pragma("unroll") \
        for (int ks = 0; ks < 6; ks++) { \
            int kb = ks * 16; \
            uint32_t ra[4][4], rb[4][2]; \
            _Pragma("unroll") \
            for (int mf = 0; mf < 4; mf++) \
                ldsm4(ra[mf][0], ra[mf][1], ra[mf][2], ra[mf][3], \
                      Ab + 2u * (uint32_t)((wm * 64 + mf * 16) * MST + aoff + kb)); \
            _Pragma("unroll") \
            for (int p = 0; p < 2; p++) \
                ldsm4(rb[2*p][0], rb[2*p][1], rb[2*p+1][0], rb[2*p+1][1], \
                      Bb + 2u * (uint32_t)((wn * 32 + p * 16) * MST + boff + kb)); \
            _Pragma("unroll") \
            for (int mf = 0; mf < 4; mf++) \
                _Pragma("unroll") \
                for (int nf = 0; nf < 4; nf++) \
                    mma16816(acc[mf][nf], ra[mf][0], ra[mf][1], ra[mf][2], ra[mf][3], \
                             rb[nf][0], rb[nf][1]); } }

    int nt = K / 32;
    LDGA(0); LDGB(0);
    CVTA(0); CVTB(0);
    for (int kt = 0; kt < nt; kt++) {
        int s = kt & 1;
        if (kt + 1 < nt) { LDGA(kt + 1); LDGB(kt + 1); }
        __syncthreads();
        MMAS(s);
        if (kt + 1 < nt) { CVTA(s ^ 1); CVTB(s ^ 1); }
    }

    #pragma unroll
    for (int mf = 0; mf < 4; mf++) {
        int row0 = rowBlk + wm * 64 + mf * 16 + g;
        #pragma unroll
        for (int nf = 0; nf < 4; nf++) {
            int col = colBlk + wn * 32 + nf * 8 + tg * 2;
            float vals[4] = {acc[mf][nf].x, acc[mf][nf].y, acc[mf][nf].z, acc[mf][nf].w};
            #pragma unroll
            for (int h = 0; h < 2; h++) {
                int row = row0 + h * 8;
                #pragma unroll
                for (int e = 0; e < 2; e++) {
                    int c = col + e;
                    if (!NGUARD || c < N) {
                        float v = vals[h * 2 + e];
                        if (bias) v += bias[c];
                        if (GELU) v = 0.5f * v * (1.0f + erff(v * 0.7071067811865476f));
                        if (res)  v += res[(size_t)row * N + c];
                        Cout[(size_t)row * N + c] = v;
                    }
                }
            }
        }
    }
#undef LDGA
#undef LDGB
#undef CVTA
#undef CVTB
#undef MMAS
}

// =========================================================================
// Fused flash attention: per (qtile 64, b*h) block, 4 warps.
// QK^T: hi/lo 3x scheme (K''=192). softmax online. P@V: Ph/Pl + Vh/Vl.
// =========================================================================
#define FA_QST 200
#define FA_KST 200
#define FA_VST 136
#define FA_SMEM ((64*FA_QST + 64*FA_KST + 64*FA_VST)*2)

__global__ void __launch_bounds__(128, 2)
attn_fused_kernel() {
    extern __shared__ __nv_bfloat16 sm[];
    __nv_bfloat16* Qs = sm;
    __nv_bfloat16* Ks = sm + 64 * FA_QST;
    __nv_bfloat16* Vs = sm + 64 * (FA_QST + FA_KST);
    int tid = threadIdx.x, lane = tid & 31, warp = tid >> 5;
    int qt = blockIdx.x, bh = blockIdx.y;
    int b = bh >> 4, h = bh & 15;
    int g = lane >> 2, tg = lane & 3;
    int t8 = lane >> 3, r8 = lane & 7;
    uint32_t sb = (uint32_t)__cvta_generic_to_shared(sm);
    uint32_t Qb = sb;
    uint32_t Kb = sb + 64 * FA_QST * 2;
    uint32_t Vb = sb + 64 * (FA_QST + FA_KST) * 2;
    int aoff = ((t8 & 1) * 8 + r8) * FA_QST + (t8 >> 1) * 8;
    int koff = ((t8 >> 1) * 8 + r8) * FA_KST + (t8 & 1) * 8;
    int voff = ((t8 >> 1) * 8 + r8) * FA_VST + (t8 & 1) * 8;

    // ---- stage Q once (scaled by 1/sqrt(HD)=0.125), hi/lo interleave + hi ----
    {
        int row = tid >> 1, seg = (tid & 1) * 32;
        const float* src = g_qkv + (size_t)(b * Tz + qt * 64 + row) * C3z + h * HDz + seg;
        uint32_t wbuf[32]; unsigned short hsb[32];
        #pragma unroll
        for (int i = 0; i < 8; i++) {
            float4 v = *(const float4*)(src + i * 4);
            float xs[4] = {v.x, v.y, v.z, v.w};
            #pragma unroll
            for (int e = 0; e < 4; e++) {
                float x = xs[e] * 0.125f;
                __nv_bfloat16 hb = __float2bfloat16(x);
                __nv_bfloat16 lb = __float2bfloat16(x - __bfloat162float(hb));
                int i4 = i * 4 + e;
                wbuf[i4] = (uint32_t)__bfloat16_as_ushort(hb) |
                           ((uint32_t)__bfloat16_as_ushort(lb) << 16);
                hsb[i4] = __bfloat16_as_ushort(hb);
            }
        }
        uint4* d0 = (uint4*)(Qs + row * FA_QST + 2 * seg);
        #pragma unroll
        for (int i = 0; i < 8; i++) d0[i] = ((const uint4*)wbuf)[i];
        uint32_t hw[16];
        #pragma unroll
        for (int j = 0; j < 16; j++)
            hw[j] = (uint32_t)hsb[2 * j] | ((uint32_t)hsb[2 * j + 1] << 16);
        uint4* d1 = (uint4*)(Qs + row * FA_QST + 128 + seg);
        #pragma unroll
        for (int i = 0; i < 4; i++) d1[i] = ((const uint4*)hw)[i];
    }

    float m0 = -1e30f, m1 = -1e30f, l0 = 0.f, l1 = 0.f;
    float4 O[8];
    #pragma unroll
    for (int i = 0; i < 8; i++) O[i] = make_float4(0.f, 0.f, 0.f, 0.f);

    for (int kt = 0; kt <= qt; kt++) {
        // ---- stage K: (kh,kh) interleave + kl ----
        {
            int row = tid >> 1, seg = (tid & 1) * 32;
            const float* src = g_qkv + (size_t)(b * Tz + kt * 64 + row) * C3z + Cz + h * HDz + seg;
            uint32_t wbuf[32]; unsigned short lsb[32];
            #pragma unroll
            for (int i = 0; i < 8; i++) {
                float4 v = *(const float4*)(src + i * 4);
                float xs[4] = {v.x, v.y, v.z, v.w};
                #pragma unroll
                for (int e = 0; e < 4; e++) {
                    float x = xs[e];
                    __nv_bfloat16 hb = __float2bfloat16(x);
                    unsigned short hu = __bfloat16_as_ushort(hb);
                    __nv_bfloat16 lb = __float2bfloat16(x - __bfloat162float(hb));
                    int i4 = i * 4 + e;
                    wbuf[i4] = (uint32_t)hu | ((uint32_t)hu << 16);
                    lsb[i4] = __bfloat16_as_ushort(lb);
                }
            }
            uint4* d0 = (uint4*)(Ks + row * FA_KST + 2 * seg);
            #pragma unroll
            for (int i = 0; i < 8; i++) d0[i] = ((const uint4*)wbuf)[i];
            uint32_t lw[16];
            #pragma unroll
            for (int j = 0; j < 16; j++)
                lw[j] = (uint32_t)lsb[2 * j] | ((uint32_t)lsb[2 * j + 1] << 16);
            uint4* d1 = (uint4*)(Ks + row * FA_KST + 128 + seg);
            #pragma unroll
            for (int i = 0; i < 4; i++) d1[i] = ((const uint4*)lw)[i];
        }
        // ---- stage V transposed: Vs[dim][key] hi | lo ----
        {
            int nd = (tid & 15) * 4;
            int k8 = (tid >> 4) * 8;
            unsigned short vh[4][8], vl[4][8];
            #pragma unroll
            for (int kk = 0; kk < 8; kk++) {
                const float* src = g_qkv + (size_t)(b * Tz + kt * 64 + k8 + kk) * C3z + 2 * Cz + h * HDz + nd;
                float4 v = *(const float4*)src;
                float xs[4] = {v.x, v.y, v.z, v.w};
                #pragma unroll
                for (int e = 0; e < 4; e++) {
                    float x = xs[e];
                    __nv_bfloat16 hb = __float2bfloat16(x);
                    __nv_bfloat16 lb = __float2bfloat16(x - __bfloat162float(hb));
                    vh[e][kk] = __bfloat16_as_ushort(hb);
                    vl[e][kk] = __bfloat16_as_ushort(lb);
                }
            }
            #pragma unroll
            for (int e = 0; e < 4; e++) {
                *(uint4*)(Vs + (nd + e) * FA_VST + k8)      = *(const uint4*)vh[e];
                *(uint4*)(Vs + (nd + e) * FA_VST + 64 + k8) = *(const uint4*)vl[e];
            }
        }
        __syncthreads();

        // ---- S = Q @ K^T (K''=192, 12 ksteps) ----
        float4 S[8];
        #pragma unroll
        for (int i = 0; i < 8; i++) S[i] = make_float4(0.f, 0.f, 0.f, 0.f);
        #pragma unroll
        for (int ks = 0; ks < 12; ks++) {
            int kb = ks * 16;
            uint32_t ra0, ra1, ra2, ra3;
            ldsm4(ra0, ra1, ra2, ra3, Qb + 2u * (uint32_t)(warp * 16 * FA_QST + aoff + kb));
            #pragma unroll
            for (int pp = 0; pp < 4; pp++) {
                uint32_t b0, b1, b2, b3;
                ldsm4(b0, b1, b2, b3, Kb + 2u * (uint32_t)((pp * 16) * FA_KST + koff + kb));
                mma16816(S[2 * pp],     ra0, ra1, ra2, ra3, b0, b1);
                mma16816(S[2 * pp + 1], ra0, ra1, ra2, ra3, b2, b3);
            }
        }

        // ---- causal mask on diagonal tile ----
        if (kt == qt) {
            int r0 = warp * 16 + g, r1 = r0 + 8;
            #pragma unroll
            for (int j = 0; j < 8; j++) {
                int c0 = j * 8 + 2 * tg, c1 = c0 + 1;
                if (c0 > r0) S[j].x = -1e30f;
                if (c1 > r0) S[j].y = -1e30f;
                if (c0 > r1) S[j].z = -1e30f;
                if (c1 > r1) S[j].w = -1e30f;
            }
        }

        // ---- online softmax ----
        float mx0 = -1e30f, mx1 = -1e30f;
        #pragma unroll
        for (int j = 0; j < 8; j++) {
            mx0 = fmaxf(mx0, fmaxf(S[j].x, S[j].y));
            mx1 = fmaxf(mx1, fmaxf(S[j].z, S[j].w));
        }
        mx0 = fmaxf(mx0, __shfl_xor_sync(0xffffffffu, mx0, 1));
        mx0 = fmaxf(mx0, __shfl_xor_sync(0xffffffffu, mx0, 2));
        mx1 = fmaxf(mx1, __shfl_xor_sync(0xffffffffu, mx1, 1));
        mx1 = fmaxf(mx1, __shfl_xor_sync(0xffffffffu, mx1, 2));
        float mn0 = fmaxf(m0, mx0), mn1 = fmaxf(m1, mx1);
        float al0 = __expf(m0 - mn0), al1 = __expf(m1 - mn1);
        m0 = mn0; m1 = mn1;
        float rs0 = 0.f, rs1 = 0.f;
        #pragma unroll
        for (int j = 0; j < 8; j++) {
            S[j].x = __expf(S[j].x - m0);
            S[j].y = __expf(S[j].y - m0);
            S[j].z = __expf(S[j].z - m1);
            S[j].w = __expf(S[j].w - m1);
            rs0 += S[j].x + S[j].y;
            rs1 += S[j].z + S[j].w;
        }
        rs0 += __shfl_xor_sync(0xffffffffu, rs0, 1);
        rs0 += __shfl_xor_sync(0xffffffffu, rs0, 2);
        rs1 += __shfl_xor_sync(0xffffffffu, rs1, 1);
        rs1 += __shfl_xor_sync(0xffffffffu, rs1, 2);
        l0 = l0 * al0 + rs0;
        l1 = l1 * al1 + rs1;
        #pragma unroll
        for (int j = 0; j < 8; j++) {
            O[j].x *= al0; O[j].y *= al0;
            O[j].z *= al1; O[j].w *= al1;
        }

        // ---- O += P @ V (Ph*Vh + Pl*Vh + Ph*Vl) ----
        #pragma unroll
        for (int kc = 0; kc < 4; kc++) {
            float4 s0 = S[2 * kc], s1 = S[2 * kc + 1];
            float f0[8] = {s0.x, s0.y, s0.z, s0.w, s1.x, s1.y, s1.z, s1.w};
            unsigned short phs[8], pls[8];
            #pragma unroll
            for (int e = 0; e < 8; e++) {
                __nv_bfloat16 hb = __float2bfloat16(f0[e]);
                phs[e] = __bfloat16_as_ushort(hb);
                pls[e] = __bfloat16_as_ushort(__float2bfloat16(f0[e] - __bfloat162float(hb)));
            }
            uint32_t ph0 = (uint32_t)phs[0] | ((uint32_t)phs[1] << 16);
            uint32_t ph1 = (uint32_t)phs[2] | ((uint32_t)phs[3] << 16);
            uint32_t ph2 = (uint32_t)phs[4] | ((uint32_t)phs[5] << 16);
            uint32_t ph3 = (uint32_t)phs[6] | ((uint32_t)phs[7] << 16);
            uint32_t pl0 = (uint32_t)pls[0] | ((uint32_t)pls[1] << 16);
            uint32_t pl1 = (uint32_t)pls[2] | ((uint32_t)pls[3] << 16);
            uint32_t pl2 = (uint32_t)pls[4] | ((uint32_t)pls[5] << 16);
            uint32_t pl3 = (uint32_t)pls[6] | ((uint32_t)pls[7] << 16);

            uint32_t vh[8][2], vl[8][2];
            #pragma unroll
            for (int pp = 0; pp < 4; pp++) {
                ldsm4(vh[2*pp][0], vh[2*pp][1], vh[2*pp+1][0], vh[2*pp+1][1],
                      Vb + 2u * (uint32_t)((pp * 16) * FA_VST + voff + kc * 16));
                ldsm4(vl[2*pp][0], vl[2*pp][1], vl[2*pp+1][0], vl[2*pp+1][1],
                      Vb + 2u * (uint32_t)((pp * 16) * FA_VST + voff + 64 + kc * 16));
            }
            #pragma unroll
            for (int nf = 0; nf < 8; nf++) {
                mma16816(O[nf], ph0, ph1, ph2, ph3, vh[nf][0], vh[nf][1]);
                mma16816(O[nf], pl0, pl1, pl2, pl3, vh[nf][0], vh[nf][1]);
                mma16816(O[nf], ph0, ph1, ph2, ph3, vl[nf][0], vl[nf][1]);
            }
        }
        __syncthreads();
    }

    // ---- finalize and store ----
    float i0 = 1.0f / l0, i1 = 1.0f / l1;
    int qrow = qt * 64 + warp * 16 + g;
    float* dst = g_y + (size_t)(b * Tz + qrow) * Cz + h * HDz;
    #pragma unroll
    for (int nf = 0; nf < 8; nf++) {
        int col = nf * 8 + 2 * tg;
        float2 v0 = make_float2(O[nf].x * i0, O[nf].y * i0);
        float2 v1 = make_float2(O[nf].z * i1, O[nf].w * i1);
        *(float2*)(dst + col) = v0;
        *(float2*)(dst + (size_t)8 * Cz + col) = v1;
    }
}

// ---------------- loss ----------------
__global__ void loss_row_kernel(const float* __restrict__ logits,
                                const int* __restrict__ targets) {
    int r = blockIdx.x;
    const float* row = logits + (size_t)r * Vz;
    int tid = threadIdx.x;
    float mx = -1e30f;
    for (int j = tid; j < Vz; j += 256) mx = fmaxf(mx, row[j]);
    mx = blockReduceMax(mx);
    float s = 0.f;
    for (int j = tid; j < Vz; j += 256) s += expf(row[j] - mx);
    s = blockReduceSum(s);
    if (tid == 0) {
        int t = targets[r];
        g_red[r] = -(row[t] - mx - logf(s));
    }
}

__global__ void loss_final_kernel(float* __restrict__ out, int out_size) {
    int tid = threadIdx.x;
    float s = 0.f;
    for (int j = tid; j < BTz; j += 256) s += g_red[j];
    s = blockReduceSum(s);
    if (tid == 0) {
        long long logits_elems = (long long)BTz * Vz;
        if ((long long)out_size > logits_elems)
            out[logits_elems] = s / (float)BTz;
    }
}

// ---------------- launch ----------------
extern "C" void kernel_launch(void* const* d_in, const int* in_sizes, int n_in,
                              void* d_out, int out_size) {
    const int*   idx     = (const int*)d_in[0];
    const int*   targets = (const int*)d_in[1];
    const float* tok_emb = (const float*)d_in[2];
    const float* pos_emb = (const float*)d_in[3];
    const float* ln1_w   = (const float*)d_in[4];
    const float* ln1_b   = (const float*)d_in[5];
    const float* ln2_w   = (const float*)d_in[6];
    const float* ln2_b   = (const float*)d_in[7];
    const float* Wq = (const float*)d_in[8];
    const float* bq = (const float*)d_in[9];
    const float* Wk = (const float*)d_in[10];
    const float* bk = (const float*)d_in[11];
    const float* Wv = (const float*)d_in[12];
    const float* bv = (const float*)d_in[13];
    const float* Wo = (const float*)d_in[14];
    const float* bo = (const float*)d_in[15];
    const float* W1 = (const float*)d_in[16];
    const float* b1 = (const float*)d_in[17];
    const float* W2 = (const float*)d_in[18];
    const float* b2 = (const float*)d_in[19];
    const float* lnf_w  = (const float*)d_in[20];
    const float* lnf_b  = (const float*)d_in[21];
    const float* head_w = (const float*)d_in[22];
    float* out = (float*)d_out;

    float *px, *ph, *pqkv, *py, *pff, *pwp, *pbp;
    cudaGetSymbolAddress((void**)&px,   g_x);
    cudaGetSymbolAddress((void**)&ph,   g_h);
    cudaGetSymbolAddress((void**)&pqkv, g_qkv);
    cudaGetSymbolAddress((void**)&py,   g_y);
    cudaGetSymbolAddress((void**)&pff,  g_ff);
    cudaGetSymbolAddress((void**)&pwp,  g_wpack);
    cudaGetSymbolAddress((void**)&pbp,  g_bpack);

    cudaFuncSetAttribute(gemm_mma_kernel<false, false>,
                         cudaFuncAttributeMaxDynamicSharedMemorySize, GSMEM);
    cudaFuncSetAttribute(gemm_mma_kernel<true, false>,
                         cudaFuncAttributeMaxDynamicSharedMemorySize, GSMEM);
    cudaFuncSetAttribute(gemm_mma_kernel<false, true>,
                         cudaFuncAttributeMaxDynamicSharedMemorySize, GSMEM);
    cudaFuncSetAttribute(attn_fused_kernel,
                         cudaFuncAttributeMaxDynamicSharedMemorySize, FA_SMEM);

    embed_kernel<<<BTz, 256>>>(idx, tok_emb, pos_emb);

    const size_t CC  = (size_t)Cz * Cz;
    const size_t C14 = (size_t)Cz * C4z;
    dim3 gQKV(C3z / 128, BTz / 128);
    dim3 gCC(Cz / 128, BTz / 128);
    dim3 gC4(C4z / 128, BTz / 128);
    dim3 gHead((Vz + 127) / 128, BTz / 128);

    for (int l = 0; l < Lz; l++) {
        pack_w_kernel<<<dim3(Cz, 3), 256>>>(Wq + l * CC, Wk + l * CC, Wv + l * CC);
        pack_b_kernel<<<3, 256>>>(bq + (size_t)l * Cz, bk + (size_t)l * Cz, bv + (size_t)l * Cz);
        ln_kernel<<<BTz, 256>>>(px, ln1_w + (size_t)l * Cz, ln1_b + (size_t)l * Cz, ph);
        gemm_mma_kernel<false, false><<<gQKV, 256, GSMEM>>>(ph, pwp, pbp, nullptr, pqkv, BTz, C3z, Cz);
        attn_fused_kernel<<<dim3(Tz / 64, Bz * Hz), 128, FA_SMEM>>>();
        gemm_mma_kernel<false, false><<<gCC, 256, GSMEM>>>(py, Wo + l * CC, bo + (size_t)l * Cz, px, px, BTz, Cz, Cz);
        ln_kernel<<<BTz, 256>>>(px, ln2_w + (size_t)l * Cz, ln2_b + (size_t)l * Cz, ph);
        gemm_mma_kernel<true , false><<<gC4, 256, GSMEM>>>(ph, W1 + l * C14, b1 + (size_t)l * C4z, nullptr, pff, BTz, C4z, Cz);
        gemm_mma_kernel<false, false><<<gCC, 256, GSMEM>>>(pff, W2 + l * C14, b2 + (size_t)l * Cz, px, px, BTz, Cz, C4z);
    }

    ln_kernel<<<BTz, 256>>>(px, lnf_w, lnf_b, ph);
    gemm_mma_kernel<false, true><<<gHead, 256, GSMEM>>>(ph, head_w, nullptr, nullptr, out, BTz, Vz, Cz);
    loss_row_kernel<<<BTz, 256>>>(out, targets);
    loss_final_kernel<<<1, 256>>>(out, out_size);
}